// round 12
// baseline (speedup 1.0000x reference)
#include <cuda_runtime.h>
#include <math.h>

#define NB 4096
#define NC 512
#define NHW 196
#define NE 64
#define TOPK 8
#define ROWS 8

// scratch: pooled [B, C] (8 MB) — __device__ global, no allocation
__device__ __align__(16) float g_pooled[NB * NC];

// packed fp32x2 FMA (SASS FFMA2 — only reachable via PTX)
#define FMA2(acc, a, b) \
    asm("fma.rn.f32x2 %0, %1, %2, %0;" : "+l"(acc) : "l"(a), "l"(b))

__device__ __forceinline__ float pair_sum(unsigned long long v) {
    return __uint_as_float((unsigned)v) + __uint_as_float((unsigned)(v >> 32));
}

// ---------------------------------------------------------------------------
// Kernel 1: global average pool (round-11 winner: proven shape + __ldcs).
// One warp per (b,c) row: 196 contiguous floats = 49 float4.
// ---------------------------------------------------------------------------
__global__ __launch_bounds__(256) void pool_kernel(const float* __restrict__ x) {
    int row = (blockIdx.x * 256 + threadIdx.x) >> 5;
    int lane = threadIdx.x & 31;

    const float4* row4 = reinterpret_cast<const float4*>(x + (size_t)row * NHW);
    float4 a = __ldcs(&row4[lane]);
    float s = (a.x + a.y) + (a.z + a.w);
    if (lane < 17) {
        float4 b4 = __ldcs(&row4[32 + lane]);
        s += (b4.x + b4.y) + (b4.z + b4.w);
    }
#pragma unroll
    for (int o = 16; o; o >>= 1) s += __shfl_xor_sync(0xffffffffu, s, o);
    if (lane == 0) g_pooled[row] = s * (1.0f / 196.0f);
}

// ---------------------------------------------------------------------------
// Kernel 2: routing (round-6 structure, E_t=4 LDS/regs optimum) with a wider
// unroll (4) to front-batch W LDGs and hide L2 latency; regs pinned to the
// 2-blocks/SM boundary via __launch_bounds__(256, 2).
// ---------------------------------------------------------------------------
__global__ void __launch_bounds__(256, 2) router_kernel(
    const float* __restrict__ noise,
    const float* __restrict__ Wr, const float* __restrict__ br,
    const float* __restrict__ Wn, const float* __restrict__ bn,
    float* __restrict__ out)
{
    __shared__ __align__(16) float sp[ROWS * NC];   // 16 KB pooled tile
    __shared__ __align__(16) float sLog[ROWS][NE];
    __shared__ __align__(16) float sNse[ROWS][NE];

    const int tid  = threadIdx.x;
    const int wid  = tid >> 5;
    const int lane = tid & 31;
    const int b0   = blockIdx.x * ROWS;

    {
        const float4* g4 = reinterpret_cast<const float4*>(g_pooled + (size_t)b0 * NC);
        float4* s4 = reinterpret_cast<float4*>(sp);
#pragma unroll
        for (int i = 0; i < ROWS * NC / 4 / 256; i++)
            s4[tid + i * 256] = g4[tid + i * 256];
    }
    __syncthreads();

    const int ph = tid & 7;        // k-phase 0..7
    const int e2 = tid >> 3;       // expert pair 0..31
    const int e0 = e2 * 2, e1 = e0 + 1;

    unsigned long long acc[ROWS][4];
#pragma unroll
    for (int r = 0; r < ROWS; r++)
#pragma unroll
        for (int m = 0; m < 4; m++) acc[r][m] = 0ull;

    const ulonglong2* Wr2 = reinterpret_cast<const ulonglong2*>(Wr);
    const ulonglong2* Wn2 = reinterpret_cast<const ulonglong2*>(Wn);
    const ulonglong2* sp2 = reinterpret_cast<const ulonglong2*>(sp);

#pragma unroll 4
    for (int j = 0; j < NC / 32; j++) {
        const int idx = j * 8 + ph;
        ulonglong2 wr0 = __ldg(&Wr2[e0 * (NC / 4) + idx]);
        ulonglong2 wr1 = __ldg(&Wr2[e1 * (NC / 4) + idx]);
        ulonglong2 wn0 = __ldg(&Wn2[e0 * (NC / 4) + idx]);
        ulonglong2 wn1 = __ldg(&Wn2[e1 * (NC / 4) + idx]);
#pragma unroll
        for (int r = 0; r < ROWS; r++) {
            ulonglong2 p = sp2[r * (NC / 4) + idx];
            FMA2(acc[r][0], p.x, wr0.x); FMA2(acc[r][0], p.y, wr0.y);
            FMA2(acc[r][1], p.x, wr1.x); FMA2(acc[r][1], p.y, wr1.y);
            FMA2(acc[r][2], p.x, wn0.x); FMA2(acc[r][2], p.y, wn0.y);
            FMA2(acc[r][3], p.x, wn1.x); FMA2(acc[r][3], p.y, wn1.y);
        }
    }

    const float br0 = br[e0], br1 = br[e1], bn0 = bn[e0], bn1 = bn[e1];
#pragma unroll
    for (int r = 0; r < ROWS; r++) {
        float vR0 = pair_sum(acc[r][0]);
        float vR1 = pair_sum(acc[r][1]);
        float vN0 = pair_sum(acc[r][2]);
        float vN1 = pair_sum(acc[r][3]);
#pragma unroll
        for (int o = 1; o < 8; o <<= 1) {
            vR0 += __shfl_xor_sync(0xffffffffu, vR0, o);
            vR1 += __shfl_xor_sync(0xffffffffu, vR1, o);
            vN0 += __shfl_xor_sync(0xffffffffu, vN0, o);
            vN1 += __shfl_xor_sync(0xffffffffu, vN1, o);
        }
        if (ph == 0) {
            sLog[r][e0] = vR0 + br0;
            sLog[r][e1] = vR1 + br1;
            sNse[r][e0] = vN0 + bn0;
            sNse[r][e1] = vN1 + bn1;
        }
    }
    __syncthreads();

    // -------- Postprocess: one warp per row; lane owns experts lane, lane+32 --
    float* out_rtr = out;
    float* out_idx = out + (size_t)NB * TOPK;
    float* out_nzy = out + (size_t)2 * NB * TOPK;

    const int r = wid;
    const int b = b0 + r;

    float lg0 = sLog[r][lane], lg1 = sLog[r][lane + 32];
    float nl0 = sNse[r][lane], nl1 = sNse[r][lane + 32];

    float m = fmaxf(lg0, lg1);
#pragma unroll
    for (int o = 16; o; o >>= 1) m = fmaxf(m, __shfl_xor_sync(0xffffffffu, m, o));
    float e0v = __expf(lg0 - m), e1v = __expf(lg1 - m);
    float s = e0v + e1v;
#pragma unroll
    for (int o = 16; o; o >>= 1) s += __shfl_xor_sync(0xffffffffu, s, o);
    float inv = __frcp_rn(s);
    float smL0 = e0v * inv, smL1 = e1v * inv;

    float sp0 = fmaxf(nl0, 0.0f) + log1pf(__expf(-fabsf(nl0)));
    float sp1 = fmaxf(nl1, 0.0f) + log1pf(__expf(-fabsf(nl1)));
    float z0 = noise[(size_t)b * NE + lane]      * sp0;
    float z1 = noise[(size_t)b * NE + lane + 32] * sp1;
    float mn = fmaxf(z0, z1);
#pragma unroll
    for (int o = 16; o; o >>= 1) mn = fmaxf(mn, __shfl_xor_sync(0xffffffffu, mn, o));
    float f0 = __expf(z0 - mn), f1 = __expf(z1 - mn);
    float sn = f0 + f1;
#pragma unroll
    for (int o = 16; o; o >>= 1) sn += __shfl_xor_sync(0xffffffffu, sn, o);
    float invn = __frcp_rn(sn);

    float noisy0 = smL0 + f0 * invn;
    float noisy1 = smL1 + f1 * invn;

    out_nzy[(size_t)b * NE + lane]      = noisy0;
    out_nzy[(size_t)b * NE + lane + 32] = noisy1;

    // top-8: iterative warp argmax; tie-break = lowest index (lax.top_k)
    float v0 = noisy0, v1 = noisy1;
    float topv[TOPK];
    int   topi[TOPK];
#pragma unroll
    for (int k = 0; k < TOPK; k++) {
        float bv; int bi;
        if (v0 >= v1) { bv = v0; bi = lane; }
        else          { bv = v1; bi = lane + 32; }
#pragma unroll
        for (int o = 16; o; o >>= 1) {
            float ov = __shfl_xor_sync(0xffffffffu, bv, o);
            int   oi = __shfl_xor_sync(0xffffffffu, bi, o);
            if (ov > bv || (ov == bv && oi < bi)) { bv = ov; bi = oi; }
        }
        topv[k] = bv; topi[k] = bi;
        if      (bi == lane)      v0 = -INFINITY;
        else if (bi == lane + 32) v1 = -INFINITY;
    }

    float ssum = 0.0f, ev[TOPK];
#pragma unroll
    for (int k = 0; k < TOPK; k++) { ev[k] = __expf(topv[k] - topv[0]); ssum += ev[k]; }
    float invt = __frcp_rn(ssum);

#pragma unroll
    for (int k = 0; k < TOPK; k++) {
        if (lane == k) {
            out_rtr[(size_t)b * TOPK + k] = ev[k] * invt;
            out_idx[(size_t)b * TOPK + k] = (float)topi[k];
        }
    }
}

// ---------------------------------------------------------------------------
extern "C" void kernel_launch(void* const* d_in, const int* in_sizes, int n_in,
                              void* d_out, int out_size) {
    const float* mh      = (const float*)d_in[0];
    const float* noise   = (const float*)d_in[1];
    const float* W_route = (const float*)d_in[2];
    const float* b_route = (const float*)d_in[3];
    const float* W_noise = (const float*)d_in[4];
    const float* b_noise = (const float*)d_in[5];
    float* out = (float*)d_out;

    pool_kernel<<<(NB * NC) / 8, 256>>>(mh);
    router_kernel<<<NB / ROWS, 256>>>(noise, W_route, b_route, W_noise, b_noise, out);
}

// round 13
// speedup vs baseline: 1.0028x; 1.0028x over previous
#include <cuda_runtime.h>
#include <math.h>

#define NB 4096
#define NC 512
#define NHW 196
#define NE 64
#define TOPK 8
#define ROWS 8

// scratch: pooled [B, C] (8 MB) — __device__ global, no allocation
__device__ __align__(16) float g_pooled[NB * NC];

// packed fp32x2 FMA (SASS FFMA2 — only reachable via PTX)
#define FMA2(acc, a, b) \
    asm("fma.rn.f32x2 %0, %1, %2, %0;" : "+l"(acc) : "l"(a), "l"(b))

__device__ __forceinline__ float pair_sum(unsigned long long v) {
    return __uint_as_float((unsigned)v) + __uint_as_float((unsigned)(v >> 32));
}

// ---------------------------------------------------------------------------
// Kernel 1: global average pool (round-11 winner: proven shape + __ldcs).
// One warp per (b,c) row: 196 contiguous floats = 49 float4.
// ---------------------------------------------------------------------------
__global__ __launch_bounds__(256) void pool_kernel(const float* __restrict__ x) {
    int row = (blockIdx.x * 256 + threadIdx.x) >> 5;
    int lane = threadIdx.x & 31;

    const float4* row4 = reinterpret_cast<const float4*>(x + (size_t)row * NHW);
    float4 a = __ldcs(&row4[lane]);
    float s = (a.x + a.y) + (a.z + a.w);
    if (lane < 17) {
        float4 b4 = __ldcs(&row4[32 + lane]);
        s += (b4.x + b4.y) + (b4.z + b4.w);
    }
#pragma unroll
    for (int o = 16; o; o >>= 1) s += __shfl_xor_sync(0xffffffffu, s, o);
    if (lane == 0) g_pooled[row] = s * (1.0f / 196.0f);
}

// ---------------------------------------------------------------------------
// Kernel 2: routing (round-6/11 structure: E_t=4, unroll 2 — the measured
// optimum) + two off-critical-path prefetches:
//   (a) noise loaded into registers at kernel entry,
//   (b) first W-load batch issued before __syncthreads().
// ---------------------------------------------------------------------------
__global__ void __launch_bounds__(256, 2) router_kernel(
    const float* __restrict__ noise,
    const float* __restrict__ Wr, const float* __restrict__ br,
    const float* __restrict__ Wn, const float* __restrict__ bn,
    float* __restrict__ out)
{
    __shared__ __align__(16) float sp[ROWS * NC];   // 16 KB pooled tile
    __shared__ __align__(16) float sLog[ROWS][NE];
    __shared__ __align__(16) float sNse[ROWS][NE];

    const int tid  = threadIdx.x;
    const int wid  = tid >> 5;
    const int lane = tid & 31;
    const int b0   = blockIdx.x * ROWS;

    const int ph = tid & 7;        // k-phase 0..7
    const int e2 = tid >> 3;       // expert pair 0..31
    const int e0 = e2 * 2, e1 = e0 + 1;

    // (a) prefetch noise for the postprocess (used only after the GEMM)
    const float nz0 = noise[(size_t)(b0 + wid) * NE + lane];
    const float nz1 = noise[(size_t)(b0 + wid) * NE + lane + 32];

    const ulonglong2* Wr2 = reinterpret_cast<const ulonglong2*>(Wr);
    const ulonglong2* Wn2 = reinterpret_cast<const ulonglong2*>(Wn);

    // (b) first W batch in flight before the smem barrier
    ulonglong2 wr0 = __ldg(&Wr2[e0 * (NC / 4) + ph]);
    ulonglong2 wr1 = __ldg(&Wr2[e1 * (NC / 4) + ph]);
    ulonglong2 wn0 = __ldg(&Wn2[e0 * (NC / 4) + ph]);
    ulonglong2 wn1 = __ldg(&Wn2[e1 * (NC / 4) + ph]);

    // load pooled tile (float4, coalesced)
    {
        const float4* g4 = reinterpret_cast<const float4*>(g_pooled + (size_t)b0 * NC);
        float4* s4 = reinterpret_cast<float4*>(sp);
#pragma unroll
        for (int i = 0; i < ROWS * NC / 4 / 256; i++)
            s4[tid + i * 256] = g4[tid + i * 256];
    }
    __syncthreads();

    unsigned long long acc[ROWS][4];
#pragma unroll
    for (int r = 0; r < ROWS; r++)
#pragma unroll
        for (int m = 0; m < 4; m++) acc[r][m] = 0ull;

    const ulonglong2* sp2 = reinterpret_cast<const ulonglong2*>(sp);

#pragma unroll 2
    for (int j = 0; j < NC / 32; j++) {
        const int idx = j * 8 + ph;
#pragma unroll
        for (int r = 0; r < ROWS; r++) {
            ulonglong2 p = sp2[r * (NC / 4) + idx];
            FMA2(acc[r][0], p.x, wr0.x); FMA2(acc[r][0], p.y, wr0.y);
            FMA2(acc[r][1], p.x, wr1.x); FMA2(acc[r][1], p.y, wr1.y);
            FMA2(acc[r][2], p.x, wn0.x); FMA2(acc[r][2], p.y, wn0.y);
            FMA2(acc[r][3], p.x, wn1.x); FMA2(acc[r][3], p.y, wn1.y);
        }
        if (j + 1 < NC / 32) {
            const int nidx = (j + 1) * 8 + ph;
            wr0 = __ldg(&Wr2[e0 * (NC / 4) + nidx]);
            wr1 = __ldg(&Wr2[e1 * (NC / 4) + nidx]);
            wn0 = __ldg(&Wn2[e0 * (NC / 4) + nidx]);
            wn1 = __ldg(&Wn2[e1 * (NC / 4) + nidx]);
        }
    }

    const float br0 = br[e0], br1 = br[e1], bn0 = bn[e0], bn1 = bn[e1];
#pragma unroll
    for (int r = 0; r < ROWS; r++) {
        float vR0 = pair_sum(acc[r][0]);
        float vR1 = pair_sum(acc[r][1]);
        float vN0 = pair_sum(acc[r][2]);
        float vN1 = pair_sum(acc[r][3]);
#pragma unroll
        for (int o = 1; o < 8; o <<= 1) {
            vR0 += __shfl_xor_sync(0xffffffffu, vR0, o);
            vR1 += __shfl_xor_sync(0xffffffffu, vR1, o);
            vN0 += __shfl_xor_sync(0xffffffffu, vN0, o);
            vN1 += __shfl_xor_sync(0xffffffffu, vN1, o);
        }
        if (ph == 0) {
            sLog[r][e0] = vR0 + br0;
            sLog[r][e1] = vR1 + br1;
            sNse[r][e0] = vN0 + bn0;
            sNse[r][e1] = vN1 + bn1;
        }
    }
    __syncthreads();

    // -------- Postprocess: one warp per row; lane owns experts lane, lane+32 --
    float* out_rtr = out;
    float* out_idx = out + (size_t)NB * TOPK;
    float* out_nzy = out + (size_t)2 * NB * TOPK;

    const int r = wid;
    const int b = b0 + r;

    float lg0 = sLog[r][lane], lg1 = sLog[r][lane + 32];
    float nl0 = sNse[r][lane], nl1 = sNse[r][lane + 32];

    float m = fmaxf(lg0, lg1);
#pragma unroll
    for (int o = 16; o; o >>= 1) m = fmaxf(m, __shfl_xor_sync(0xffffffffu, m, o));
    float e0v = __expf(lg0 - m), e1v = __expf(lg1 - m);
    float s = e0v + e1v;
#pragma unroll
    for (int o = 16; o; o >>= 1) s += __shfl_xor_sync(0xffffffffu, s, o);
    float inv = __frcp_rn(s);
    float smL0 = e0v * inv, smL1 = e1v * inv;

    float sp0 = fmaxf(nl0, 0.0f) + log1pf(__expf(-fabsf(nl0)));
    float sp1 = fmaxf(nl1, 0.0f) + log1pf(__expf(-fabsf(nl1)));
    float z0 = nz0 * sp0;
    float z1 = nz1 * sp1;
    float mn = fmaxf(z0, z1);
#pragma unroll
    for (int o = 16; o; o >>= 1) mn = fmaxf(mn, __shfl_xor_sync(0xffffffffu, mn, o));
    float f0 = __expf(z0 - mn), f1 = __expf(z1 - mn);
    float sn = f0 + f1;
#pragma unroll
    for (int o = 16; o; o >>= 1) sn += __shfl_xor_sync(0xffffffffu, sn, o);
    float invn = __frcp_rn(sn);

    float noisy0 = smL0 + f0 * invn;
    float noisy1 = smL1 + f1 * invn;

    out_nzy[(size_t)b * NE + lane]      = noisy0;
    out_nzy[(size_t)b * NE + lane + 32] = noisy1;

    // top-8: iterative warp argmax; tie-break = lowest index (lax.top_k)
    float v0 = noisy0, v1 = noisy1;
    float topv[TOPK];
    int   topi[TOPK];
#pragma unroll
    for (int k = 0; k < TOPK; k++) {
        float bv; int bi;
        if (v0 >= v1) { bv = v0; bi = lane; }
        else          { bv = v1; bi = lane + 32; }
#pragma unroll
        for (int o = 16; o; o >>= 1) {
            float ov = __shfl_xor_sync(0xffffffffu, bv, o);
            int   oi = __shfl_xor_sync(0xffffffffu, bi, o);
            if (ov > bv || (ov == bv && oi < bi)) { bv = ov; bi = oi; }
        }
        topv[k] = bv; topi[k] = bi;
        if      (bi == lane)      v0 = -INFINITY;
        else if (bi == lane + 32) v1 = -INFINITY;
    }

    float ssum = 0.0f, ev[TOPK];
#pragma unroll
    for (int k = 0; k < TOPK; k++) { ev[k] = __expf(topv[k] - topv[0]); ssum += ev[k]; }
    float invt = __frcp_rn(ssum);

#pragma unroll
    for (int k = 0; k < TOPK; k++) {
        if (lane == k) {
            out_rtr[(size_t)b * TOPK + k] = ev[k] * invt;
            out_idx[(size_t)b * TOPK + k] = (float)topi[k];
        }
    }
}

// ---------------------------------------------------------------------------
extern "C" void kernel_launch(void* const* d_in, const int* in_sizes, int n_in,
                              void* d_out, int out_size) {
    const float* mh      = (const float*)d_in[0];
    const float* noise   = (const float*)d_in[1];
    const float* W_route = (const float*)d_in[2];
    const float* b_route = (const float*)d_in[3];
    const float* W_noise = (const float*)d_in[4];
    const float* b_noise = (const float*)d_in[5];
    float* out = (float*)d_out;

    pool_kernel<<<(NB * NC) / 8, 256>>>(mh);
    router_kernel<<<NB / ROWS, 256>>>(noise, W_route, b_route, W_noise, b_noise, out);
}